// round 1
// baseline (speedup 1.0000x reference)
#include <cuda_runtime.h>
#include <cstdint>

#define N_FINE   200000
#define N_COARSE 50000
#define ROW_F4   128   // 2*128*2 floats / 4 = 128 float4 per node row

// Inverse permutation table: unpool_map[fine_id] = coarse_idx.
// Zero-initialized at module load; entries never named by unpool_nodes stay 0
// (matching the reference's jnp.zeros init). The scatter below writes the same
// values on every replay -> deterministic & graph-safe.
__device__ int g_unpool_map[N_FINE];

__global__ void build_map_kernel(const int* __restrict__ nodes) {
    int i = blockIdx.x * blockDim.x + threadIdx.x;
    if (i < N_COARSE) {
        g_unpool_map[nodes[i]] = i;
    }
}

// One edge = one 2048-byte row. 128 threads per edge, one float4 each.
// float4 k covers floats 4k..4k+3 of the row [2][128][2]:
//   k <  64 : group 0  -> straight copy
//   k >= 64 : group 1  -> complex multiply by conj(cos,sin):
//             re' = re*c + im*s ; im' = -re*s + im*c
__global__ void unpool_kernel(const float4* __restrict__ x,
                              const float2* __restrict__ conn,
                              const int*    __restrict__ edge_src,
                              const int*    __restrict__ edge_dst,
                              float4*       __restrict__ out) {
    int t = blockIdx.x * blockDim.x + threadIdx.x;
    int e = t >> 7;        // edge index
    int j = t & 127;       // float4 index within the row
    if (e >= N_FINE) return;

    int src = g_unpool_map[edge_src[e]];   // coarse row to gather
    int dst = edge_dst[e];                 // fine row to scatter

    float4 v = x[(size_t)src * ROW_F4 + j];

    if (j >= 64) {
        float2 cs = conn[e];
        float c = cs.x, s = cs.y;
        float4 r;
        r.x = fmaf(v.x, c, v.y * s);
        r.y = fmaf(v.y, c, -v.x * s);
        r.z = fmaf(v.z, c, v.w * s);
        r.w = fmaf(v.w, c, -v.z * s);
        v = r;
    }

    out[(size_t)dst * ROW_F4 + j] = v;
}

extern "C" void kernel_launch(void* const* d_in, const int* in_sizes, int n_in,
                              void* d_out, int out_size) {
    // metadata order: x, unpool_connection, unpool_nodes, unpool_edges, num_nodes
    const float4* x     = (const float4*)d_in[0];
    const float2* conn  = (const float2*)d_in[1];
    const int*    nodes = (const int*)d_in[2];
    const int*    edges = (const int*)d_in[3];   // [2, N_FINE]: row0=src, row1=dst
    float4*       out   = (float4*)d_out;

    (void)in_sizes; (void)n_in; (void)out_size;

    build_map_kernel<<<(N_COARSE + 255) / 256, 256>>>(nodes);

    const long long total = (long long)N_FINE * ROW_F4;   // 25.6M threads
    unpool_kernel<<<(unsigned)((total + 255) / 256), 256>>>(
        x, conn, edges, edges + N_FINE, out);
}

// round 2
// speedup vs baseline: 1.3875x; 1.3875x over previous
#include <cuda_runtime.h>
#include <cstdint>

#define N_FINE   200000
#define N_COARSE 50000
#define ROW_F4   128   // (2 groups * 128 ch * 2 cplx) floats / 4 = 128 float4 per row

// ---------- device scratch (no runtime allocation allowed) ----------
__device__ int g_unpool_map[N_FINE];   // zero-init matches jnp.zeros in reference

struct __align__(16) EdgeRec { int src; int dst; float c; float s; };
__device__ EdgeRec g_edge[N_FINE];     // 3.2 MB: fully resolved per-edge record

// ---------- phase 1: inverse permutation ----------
__global__ void build_map_kernel(const int* __restrict__ nodes) {
    int i = blockIdx.x * blockDim.x + threadIdx.x;
    if (i < N_COARSE) g_unpool_map[nodes[i]] = i;
}

// ---------- phase 2: resolve edges -> {coarse src row, fine dst row, cos, sin} ----------
__global__ void build_edge_kernel(const int*    __restrict__ edge_src,
                                  const int*    __restrict__ edge_dst,
                                  const float2* __restrict__ conn) {
    int e = blockIdx.x * blockDim.x + threadIdx.x;
    if (e < N_FINE) {
        EdgeRec r;
        r.src = g_unpool_map[edge_src[e]];
        r.dst = edge_dst[e];
        float2 cs = conn[e];
        r.c = cs.x;
        r.s = cs.y;
        g_edge[e] = r;
    }
}

// ---------- phase 3: gather row, rotate group 1, scatter ----------
// 64 threads per edge; thread j handles float4 j (group 0, plain copy) and
// float4 j+64 (group 1, multiply by conj(c,s)). No divergence, MLP=2.
// Output stores use streaming hint so the touch-once writes don't evict the
// heavily-reused x working set (102 MB) from L2 (126 MB).
__global__ void __launch_bounds__(256)
unpool_kernel(const float4* __restrict__ x, float4* __restrict__ out) {
    int t = blockIdx.x * blockDim.x + threadIdx.x;
    int e = t >> 6;        // edge index (uniform per warp-half; uniform loads below)
    int j = t & 63;        // float4 lane within first half of the row
    if (e >= N_FINE) return;

    // Single 16-byte load for all per-edge metadata.
    int4 raw = *reinterpret_cast<const int4*>(&g_edge[e]);
    int   src = raw.x;
    int   dst = raw.y;
    float c   = __int_as_float(raw.z);
    float s   = __int_as_float(raw.w);

    const float4* xr = x + (size_t)src * ROW_F4;
    float4 v0 = xr[j];          // group 0
    float4 v1 = xr[j + 64];     // group 1

    // (re + i*im) * (c - i*s)
    float4 r1;
    r1.x = fmaf(v1.x, c,  v1.y * s);
    r1.y = fmaf(v1.y, c, -v1.x * s);
    r1.z = fmaf(v1.z, c,  v1.w * s);
    r1.w = fmaf(v1.w, c, -v1.z * s);

    float4* o = out + (size_t)dst * ROW_F4;
    __stcs(o + j,      v0);
    __stcs(o + j + 64, r1);
}

extern "C" void kernel_launch(void* const* d_in, const int* in_sizes, int n_in,
                              void* d_out, int out_size) {
    // metadata order: x, unpool_connection, unpool_nodes, unpool_edges, num_nodes
    const float4* x     = (const float4*)d_in[0];
    const float2* conn  = (const float2*)d_in[1];
    const int*    nodes = (const int*)d_in[2];
    const int*    edges = (const int*)d_in[3];   // [2, N_FINE]: row0=src, row1=dst
    float4*       out   = (float4*)d_out;

    (void)in_sizes; (void)n_in; (void)out_size;

    build_map_kernel<<<(N_COARSE + 255) / 256, 256>>>(nodes);
    build_edge_kernel<<<(N_FINE + 255) / 256, 256>>>(edges, edges + N_FINE, conn);

    const long long total = (long long)N_FINE * 64;   // 12.8M threads
    unpool_kernel<<<(unsigned)((total + 255) / 256), 256>>>(x, out);
}